// round 7
// baseline (speedup 1.0000x reference)
#include <cuda_runtime.h>
#include <cstdint>
#include <math.h>

#define N_FEAT 120
#define M_COLS 128
#define GS_STRIDE 256
#define ATOMS_PER_BLOCK 256
#define THREADS 512

// Precomputed linear map: out[z,w] = sum_k G[z,k] * g_M[k*M_COLS + w]
__device__ float g_M[N_FEAT * M_COLS];

// ---------------------------------------------------------------------------
// Prep kernel: fold field_features + all weights into M[120][128] (cols >=120 zero)
// ---------------------------------------------------------------------------
__global__ void build_M_kernel(const float* __restrict__ f,
                               const float* __restrict__ w000,
                               const float* __restrict__ w011,
                               const float* __restrict__ w101,
                               const float* __restrict__ w110,
                               const float* __restrict__ w112,
                               const float* __restrict__ w202,
                               const float* __restrict__ w211,
                               const float* __restrict__ wl0,
                               const float* __restrict__ wl1,
                               const float* __restrict__ wl2) {
    int idx = blockIdx.x * blockDim.x + threadIdx.x;
    if (idx >= N_FEAT * M_COLS) return;
    int k = idx / M_COLS;   // input feature index
    int w = idx % M_COLS;   // output feature index (padded)
    if (w >= N_FEAT) { g_M[idx] = 0.f; return; }

    // Wigner 3j (1,1,2) coefficients, scaled by 1/sqrt(5)
    double Cw[3][3][5];
    #pragma unroll
    for (int a = 0; a < 3; a++)
        #pragma unroll
        for (int b = 0; b < 3; b++)
            #pragma unroll
            for (int c = 0; c < 5; c++) Cw[a][b][c] = 0.0;
    {
        double s2 = 1.0 / sqrt(2.0), s6 = 1.0 / sqrt(6.0);
        Cw[0][2][0] = s2;  Cw[2][0][0] = s2;
        Cw[0][1][1] = s2;  Cw[1][0][1] = s2;
        Cw[1][1][2] = 2.0 * s6; Cw[0][0][2] = -s6; Cw[2][2][2] = -s6;
        Cw[1][2][3] = s2;  Cw[2][1][3] = s2;
        Cw[2][2][4] = s2;  Cw[0][0][4] = -s2;
        double n5 = 1.0 / sqrt(5.0);
        for (int a = 0; a < 3; a++)
            for (int b = 0; b < 3; b++)
                for (int c = 0; c < 5; c++) Cw[a][b][c] *= n5;
    }

    const double INV_S3 = 1.0 / sqrt(3.0);
    const double INV_S5 = 1.0 / sqrt(5.0);
    const double C0v = sqrt(1.0 / 1280.0);  // sqrt(1/(32*32+16*16))
    const double C1v = sqrt(3.0 / 1152.0);  // sqrt(3/(32*16+16*32+8*16))
    const double C2v = sqrt(5.0 / 512.0);   // sqrt(5/(16*16+8*32))

    double val = 0.0;

    if (k < 32) {                       // input is g0[u]
        int u = k;
        if (w < 32) {                   // -> out0[wo]  (w_000 + wl0)
            int wo = w;
            double s = 0.0;
            for (int v = 0; v < 32; v++) s += (double)w000[u*1024 + v*32 + wo] * (double)f[v];
            val = C0v * s + (double)wl0[u*32 + wo] * (1.0 / sqrt(32.0));
        } else if (w < 80) {            // -> out1[wo,j]  (w_011)
            int wo = (w - 32) / 3, j = (w - 32) % 3;
            double s = 0.0;
            for (int v = 0; v < 16; v++) s += (double)w011[u*256 + v*16 + wo] * (double)f[32 + v*3 + j];
            val = C1v * INV_S3 * s;
        }
        // g0 -> out2 : zero
    } else if (k < 80) {                // input is g1[u,i]
        int u = (k - 32) / 3, i = (k - 32) % 3;
        if (w < 32) {                   // -> out0[wo]  (w_110)
            int wo = w;
            double s = 0.0;
            for (int v = 0; v < 16; v++) s += (double)w110[u*512 + v*32 + wo] * (double)f[32 + v*3 + i];
            val = C0v * INV_S3 * s;
        } else if (w < 80) {            // -> out1[wo,j]  (w_101 + wl1, only j==i)
            int wo = (w - 32) / 3, j = (w - 32) % 3;
            if (j == i) {
                double s = 0.0;
                for (int v = 0; v < 32; v++) s += (double)w101[u*512 + v*16 + wo] * (double)f[v];
                val = C1v * INV_S3 * s + (double)wl1[u*16 + wo] * 0.25;
            }
        } else {                        // -> out2[wo,kout]  (w_112 x W3J)
            int wo = (w - 80) / 5, kout = (w - 80) % 5;
            double s = 0.0;
            for (int v = 0; v < 16; v++)
                for (int j2 = 0; j2 < 3; j2++)
                    s += (double)w112[u*128 + v*8 + wo] * Cw[i][j2][kout] * (double)f[32 + v*3 + j2];
            val = C2v * s;
        }
    } else {                            // input is g2[u,i], i in 0..4
        int u = (k - 80) / 5, i = (k - 80) % 5;
        if (w >= 32 && w < 80) {        // -> out1[wo,j]  (w_211 x W3J)
            int wo = (w - 32) / 3, j = (w - 32) % 3;
            double s = 0.0;
            for (int v = 0; v < 16; v++)
                for (int i2 = 0; i2 < 3; i2++)
                    s += (double)w211[u*256 + v*16 + wo] * Cw[i2][j][i] * (double)f[32 + v*3 + i2];
            val = C1v * s;
        } else if (w >= 80) {           // -> out2[wo,j]  (w_202 + wl2, only j==i)
            int wo = (w - 80) / 5, j = (w - 80) % 5;
            if (j == i) {
                double s = 0.0;
                for (int v = 0; v < 32; v++) s += (double)w202[u*256 + v*8 + wo] * (double)f[v];
                val = C2v * INV_S5 * s + (double)wl2[u*8 + wo] * (1.0 / sqrt(8.0));
            }
        }
        // g2 -> out0 : zero
    }

    g_M[idx] = (float)val;
}

// ---------------------------------------------------------------------------
// Main kernel: out[N,120] = G[N,120] @ M, shared-memory GEMM with f32x2.
// G tile transposed + XOR swizzle: word(k,a) = k*256 + (a ^ (((k>>2)&7)<<2)).
// Thread tile: 8 atoms x 4 output-pairs. NOTE: under the XOR swizzle the two
// 4-atom halves of a thread's group are at (a0^s) and ((a0+4)^s) = (a0^s)^4 —
// NOT adjacent. Both addresses computed explicitly.
// Warp = 16 cols x 2 atom-groups:
//   - each m LDS.64 reads 32 consecutive words (1 wavefront)
//   - each g LDS.128 reads 2 distinct 16B rows (1 wavefront)
// k+1 m/g register double-buffer hides LDS latency.
// ---------------------------------------------------------------------------
__global__ __launch_bounds__(THREADS, 1)
void coupling_gemm_kernel(const float* __restrict__ G, float* __restrict__ out, int n) {
    extern __shared__ float smem[];
    float* gs = smem;                             // [120][GS_STRIDE] swizzled transposed G tile
    float* Ms = smem + N_FEAT * GS_STRIDE;        // [120][128]

    int tid = threadIdx.x;
    int atom0 = blockIdx.x * ATOMS_PER_BLOCK;

    // Load M into smem (coalesced, conflict-free)
    for (int i = tid; i < N_FEAT * M_COLS; i += THREADS) Ms[i] = g_M[i];

    // Load G tile with LDG.128, scatter-transpose with swizzle.
    {
        const float4* G4 = reinterpret_cast<const float4*>(G);
        for (int i = tid; i < ATOMS_PER_BLOCK * (N_FEAT / 4); i += THREADS) {
            int a = i / (N_FEAT / 4), kq = i % (N_FEAT / 4);
            int ga = atom0 + a;
            float4 v = make_float4(0.f, 0.f, 0.f, 0.f);
            if (ga < n) v = G4[(size_t)ga * (N_FEAT / 4) + kq];
            int as = a ^ ((kq & 7) << 2);          // swizzled atom column
            int k0 = kq * 4;
            gs[(k0 + 0) * GS_STRIDE + as] = v.x;
            gs[(k0 + 1) * GS_STRIDE + as] = v.y;
            gs[(k0 + 2) * GS_STRIDE + as] = v.z;
            gs[(k0 + 3) * GS_STRIDE + as] = v.w;
        }
    }
    __syncthreads();

    int col = tid & 15;         // 0..15 : output-pair column group
    int a0  = (tid >> 4) * 8;   // first atom of this thread's 8-atom group

    // 8 atoms x 4 output-pairs, packed f32x2 accumulators
    unsigned long long acc[8][4];
    #pragma unroll
    for (int a = 0; a < 8; a++)
        #pragma unroll
        for (int p = 0; p < 4; p++) acc[a][p] = 0ULL;

    uint32_t gs_base, ms_base;
    asm("{ .reg .u64 t; cvta.to.shared.u64 t, %1; cvt.u32.u64 %0, t; }"
        : "=r"(gs_base) : "l"(gs));
    asm("{ .reg .u64 t; cvta.to.shared.u64 t, %1; cvt.u32.u64 %0, t; }"
        : "=r"(ms_base) : "l"(Ms));
    uint32_t maddr0 = ms_base + (uint32_t)(col * 2) * 4u;

    // swizzled addresses of the two 4-atom halves for feature k
    #define G_ADDR0(k) (gs_base + (uint32_t)((k) * GS_STRIDE + ( a0      ^ ((((k) >> 2) & 7) << 2))) * 4u)
    #define G_ADDR1(k) (gs_base + (uint32_t)((k) * GS_STRIDE + ((a0 + 4) ^ ((((k) >> 2) & 7) << 2))) * 4u)
    #define M_ADDR(k) (maddr0 + (uint32_t)(k) * (M_COLS * 4u))

    float4 gc0, gc1;
    unsigned long long mc0, mc1, mc2, mc3;
    {
        uint32_t ga0 = G_ADDR0(0), ga1 = G_ADDR1(0), ma = M_ADDR(0);
        asm("ld.shared.v4.f32 {%0,%1,%2,%3}, [%4];"
            : "=f"(gc0.x), "=f"(gc0.y), "=f"(gc0.z), "=f"(gc0.w) : "r"(ga0));
        asm("ld.shared.v4.f32 {%0,%1,%2,%3}, [%4];"
            : "=f"(gc1.x), "=f"(gc1.y), "=f"(gc1.z), "=f"(gc1.w) : "r"(ga1));
        asm("ld.shared.b64 %0, [%1];" : "=l"(mc0) : "r"(ma));
        asm("ld.shared.b64 %0, [%1];" : "=l"(mc1) : "r"(ma + 128u));
        asm("ld.shared.b64 %0, [%1];" : "=l"(mc2) : "r"(ma + 256u));
        asm("ld.shared.b64 %0, [%1];" : "=l"(mc3) : "r"(ma + 384u));
    }

    #pragma unroll 4
    for (int k = 0; k < N_FEAT; k++) {
        float4 gn0, gn1;
        unsigned long long mn0, mn1, mn2, mn3;
        if (k + 1 < N_FEAT) {
            uint32_t ga0 = G_ADDR0(k + 1), ga1 = G_ADDR1(k + 1), ma = M_ADDR(k + 1);
            asm("ld.shared.v4.f32 {%0,%1,%2,%3}, [%4];"
                : "=f"(gn0.x), "=f"(gn0.y), "=f"(gn0.z), "=f"(gn0.w) : "r"(ga0));
            asm("ld.shared.v4.f32 {%0,%1,%2,%3}, [%4];"
                : "=f"(gn1.x), "=f"(gn1.y), "=f"(gn1.z), "=f"(gn1.w) : "r"(ga1));
            asm("ld.shared.b64 %0, [%1];" : "=l"(mn0) : "r"(ma));
            asm("ld.shared.b64 %0, [%1];" : "=l"(mn1) : "r"(ma + 128u));
            asm("ld.shared.b64 %0, [%1];" : "=l"(mn2) : "r"(ma + 256u));
            asm("ld.shared.b64 %0, [%1];" : "=l"(mn3) : "r"(ma + 384u));
        }

        // duplicate 8 g scalars into f32x2 packs and accumulate
        unsigned long long gd[8];
        asm("mov.b64 %0, {%1, %1};" : "=l"(gd[0]) : "f"(gc0.x));
        asm("mov.b64 %0, {%1, %1};" : "=l"(gd[1]) : "f"(gc0.y));
        asm("mov.b64 %0, {%1, %1};" : "=l"(gd[2]) : "f"(gc0.z));
        asm("mov.b64 %0, {%1, %1};" : "=l"(gd[3]) : "f"(gc0.w));
        asm("mov.b64 %0, {%1, %1};" : "=l"(gd[4]) : "f"(gc1.x));
        asm("mov.b64 %0, {%1, %1};" : "=l"(gd[5]) : "f"(gc1.y));
        asm("mov.b64 %0, {%1, %1};" : "=l"(gd[6]) : "f"(gc1.z));
        asm("mov.b64 %0, {%1, %1};" : "=l"(gd[7]) : "f"(gc1.w));

        #pragma unroll
        for (int a = 0; a < 8; a++) {
            asm("fma.rn.f32x2 %0, %1, %2, %0;" : "+l"(acc[a][0]) : "l"(gd[a]), "l"(mc0));
            asm("fma.rn.f32x2 %0, %1, %2, %0;" : "+l"(acc[a][1]) : "l"(gd[a]), "l"(mc1));
            asm("fma.rn.f32x2 %0, %1, %2, %0;" : "+l"(acc[a][2]) : "l"(gd[a]), "l"(mc2));
            asm("fma.rn.f32x2 %0, %1, %2, %0;" : "+l"(acc[a][3]) : "l"(gd[a]), "l"(mc3));
        }

        if (k + 1 < N_FEAT) {
            gc0 = gn0; gc1 = gn1;
            mc0 = mn0; mc1 = mn1; mc2 = mn2; mc3 = mn3;
        }
    }
    #undef G_ADDR0
    #undef G_ADDR1
    #undef M_ADDR

    // Store: pair p of this thread -> w = p*32 + col*2 (skip padded w >= 120)
    #pragma unroll
    for (int a = 0; a < 8; a++) {
        int atom = atom0 + a0 + a;
        if (atom < n) {
            float* orow = out + (size_t)atom * N_FEAT;
            #pragma unroll
            for (int p = 0; p < 4; p++) {
                int w = p * 32 + col * 2;
                if (w < N_FEAT) {
                    float2 v;
                    asm("mov.b64 {%0, %1}, %2;" : "=f"(v.x), "=f"(v.y) : "l"(acc[a][p]));
                    *reinterpret_cast<float2*>(orow + w) = v;
                }
            }
        }
    }
}

// ---------------------------------------------------------------------------
extern "C" void kernel_launch(void* const* d_in, const int* in_sizes, int n_in,
                              void* d_out, int out_size) {
    const float* G    = (const float*)d_in[0];
    const float* f    = (const float*)d_in[1];
    const float* w000 = (const float*)d_in[2];
    const float* w011 = (const float*)d_in[3];
    const float* w101 = (const float*)d_in[4];
    const float* w110 = (const float*)d_in[5];
    const float* w112 = (const float*)d_in[6];
    const float* w202 = (const float*)d_in[7];
    const float* w211 = (const float*)d_in[8];
    const float* wl0  = (const float*)d_in[9];
    const float* wl1  = (const float*)d_in[10];
    const float* wl2  = (const float*)d_in[11];
    float* out = (float*)d_out;

    int n = in_sizes[0] / N_FEAT;

    build_M_kernel<<<(N_FEAT * M_COLS + 127) / 128, 128>>>(
        f, w000, w011, w101, w110, w112, w202, w211, wl0, wl1, wl2);

    int smem_bytes = (N_FEAT * GS_STRIDE + N_FEAT * M_COLS) * (int)sizeof(float);
    cudaFuncSetAttribute(coupling_gemm_kernel,
                         cudaFuncAttributeMaxDynamicSharedMemorySize, smem_bytes);
    int blocks = (n + ATOMS_PER_BLOCK - 1) / ATOMS_PER_BLOCK;
    coupling_gemm_kernel<<<blocks, THREADS, smem_bytes>>>(G, out, n);
}

// round 9
// speedup vs baseline: 1.8841x; 1.8841x over previous
#include <cuda_runtime.h>
#include <cuda_bf16.h>
#include <cstdint>
#include <math.h>

#define N_FEAT 120
#define M_COLS 128
#define TILE_M 128
#define THREADS 256
#define GRID_CTAS 148

#define LDAB 136              // bf16 stride for A/B smem rows (272 bytes)
#define AB_BYTES (128 * LDAB * 2)   // 34816

// smem offsets
#define SM_A_HI 0
#define SM_A_LO AB_BYTES
#define SM_B_HI (2 * AB_BYTES)
#define SM_B_LO (3 * AB_BYTES)
#define SM_TOTAL (4 * AB_BYTES)     // 139264

// Precomputed linear map: out[z,w] = sum_k G[z,k] * g_M[k*M_COLS + w]
__device__ float g_M[N_FEAT * M_COLS];
// Pre-built bf16 hi/lo B images: B[nrow][k] = M[k][nrow], [128][LDAB]
__device__ __align__(16) __nv_bfloat16 g_Bhi[128 * LDAB];
__device__ __align__(16) __nv_bfloat16 g_Blo[128 * LDAB];

// ---------------------------------------------------------------------------
// Prep 1: fold field_features + all weights into M[120][128] (cols >=120 zero)
// ---------------------------------------------------------------------------
__global__ void build_M_kernel(const float* __restrict__ f,
                               const float* __restrict__ w000,
                               const float* __restrict__ w011,
                               const float* __restrict__ w101,
                               const float* __restrict__ w110,
                               const float* __restrict__ w112,
                               const float* __restrict__ w202,
                               const float* __restrict__ w211,
                               const float* __restrict__ wl0,
                               const float* __restrict__ wl1,
                               const float* __restrict__ wl2) {
    int idx = blockIdx.x * blockDim.x + threadIdx.x;
    if (idx >= N_FEAT * M_COLS) return;
    int k = idx / M_COLS;
    int w = idx % M_COLS;
    if (w >= N_FEAT) { g_M[idx] = 0.f; return; }

    double Cw[3][3][5];
    #pragma unroll
    for (int a = 0; a < 3; a++)
        #pragma unroll
        for (int b = 0; b < 3; b++)
            #pragma unroll
            for (int c = 0; c < 5; c++) Cw[a][b][c] = 0.0;
    {
        double s2 = 1.0 / sqrt(2.0), s6 = 1.0 / sqrt(6.0);
        Cw[0][2][0] = s2;  Cw[2][0][0] = s2;
        Cw[0][1][1] = s2;  Cw[1][0][1] = s2;
        Cw[1][1][2] = 2.0 * s6; Cw[0][0][2] = -s6; Cw[2][2][2] = -s6;
        Cw[1][2][3] = s2;  Cw[2][1][3] = s2;
        Cw[2][2][4] = s2;  Cw[0][0][4] = -s2;
        double n5 = 1.0 / sqrt(5.0);
        for (int a = 0; a < 3; a++)
            for (int b = 0; b < 3; b++)
                for (int c = 0; c < 5; c++) Cw[a][b][c] *= n5;
    }

    const double INV_S3 = 1.0 / sqrt(3.0);
    const double INV_S5 = 1.0 / sqrt(5.0);
    const double C0v = sqrt(1.0 / 1280.0);
    const double C1v = sqrt(3.0 / 1152.0);
    const double C2v = sqrt(5.0 / 512.0);

    double val = 0.0;

    if (k < 32) {
        int u = k;
        if (w < 32) {
            int wo = w;
            double s = 0.0;
            for (int v = 0; v < 32; v++) s += (double)w000[u*1024 + v*32 + wo] * (double)f[v];
            val = C0v * s + (double)wl0[u*32 + wo] * (1.0 / sqrt(32.0));
        } else if (w < 80) {
            int wo = (w - 32) / 3, j = (w - 32) % 3;
            double s = 0.0;
            for (int v = 0; v < 16; v++) s += (double)w011[u*256 + v*16 + wo] * (double)f[32 + v*3 + j];
            val = C1v * INV_S3 * s;
        }
    } else if (k < 80) {
        int u = (k - 32) / 3, i = (k - 32) % 3;
        if (w < 32) {
            int wo = w;
            double s = 0.0;
            for (int v = 0; v < 16; v++) s += (double)w110[u*512 + v*32 + wo] * (double)f[32 + v*3 + i];
            val = C0v * INV_S3 * s;
        } else if (w < 80) {
            int wo = (w - 32) / 3, j = (w - 32) % 3;
            if (j == i) {
                double s = 0.0;
                for (int v = 0; v < 32; v++) s += (double)w101[u*512 + v*16 + wo] * (double)f[v];
                val = C1v * INV_S3 * s + (double)wl1[u*16 + wo] * 0.25;
            }
        } else {
            int wo = (w - 80) / 5, kout = (w - 80) % 5;
            double s = 0.0;
            for (int v = 0; v < 16; v++)
                for (int j2 = 0; j2 < 3; j2++)
                    s += (double)w112[u*128 + v*8 + wo] * Cw[i][j2][kout] * (double)f[32 + v*3 + j2];
            val = C2v * s;
        }
    } else {
        int u = (k - 80) / 5, i = (k - 80) % 5;
        if (w >= 32 && w < 80) {
            int wo = (w - 32) / 3, j = (w - 32) % 3;
            double s = 0.0;
            for (int v = 0; v < 16; v++)
                for (int i2 = 0; i2 < 3; i2++)
                    s += (double)w211[u*256 + v*16 + wo] * Cw[i2][j][i] * (double)f[32 + v*3 + i2];
            val = C1v * s;
        } else if (w >= 80) {
            int wo = (w - 80) / 5, j = (w - 80) % 5;
            if (j == i) {
                double s = 0.0;
                for (int v = 0; v < 32; v++) s += (double)w202[u*256 + v*8 + wo] * (double)f[v];
                val = C2v * INV_S5 * s + (double)wl2[u*8 + wo] * (1.0 / sqrt(8.0));
            }
        }
    }

    g_M[idx] = (float)val;
}

// ---------------------------------------------------------------------------
// Prep 2: B[nrow][k] = M[k][nrow], bf16 hi/lo, [128][LDAB] padded images
// ---------------------------------------------------------------------------
__global__ void build_B_kernel() {
    int idx = blockIdx.x * blockDim.x + threadIdx.x;
    if (idx >= 128 * LDAB) return;
    int nrow = idx / LDAB;
    int k = idx % LDAB;
    float v = (k < N_FEAT) ? g_M[k * M_COLS + nrow] : 0.f;
    __nv_bfloat16 hi = __float2bfloat16(v);
    __nv_bfloat16 lo = __float2bfloat16(v - __bfloat162float(hi));
    g_Bhi[idx] = hi;
    g_Blo[idx] = lo;
}

// ---------------------------------------------------------------------------
// mma helpers
// ---------------------------------------------------------------------------
__device__ __forceinline__ void mma_bf16(float* c, const uint32_t* a, const uint32_t* b) {
    asm volatile(
        "mma.sync.aligned.m16n8k16.row.col.f32.bf16.bf16.f32 "
        "{%0,%1,%2,%3}, {%4,%5,%6,%7}, {%8,%9}, {%0,%1,%2,%3};"
        : "+f"(c[0]), "+f"(c[1]), "+f"(c[2]), "+f"(c[3])
        : "r"(a[0]), "r"(a[1]), "r"(a[2]), "r"(a[3]), "r"(b[0]), "r"(b[1]));
}

__device__ __forceinline__ void ldmatrix_x4(uint32_t* r, uint32_t addr) {
    asm volatile("ldmatrix.sync.aligned.m8n8.x4.shared.b16 {%0,%1,%2,%3}, [%4];"
                 : "=r"(r[0]), "=r"(r[1]), "=r"(r[2]), "=r"(r[3]) : "r"(addr));
}

__device__ __forceinline__ uint32_t lds32(uint32_t addr) {
    uint32_t v;
    asm volatile("ld.shared.b32 %0, [%1];" : "=r"(v) : "r"(addr));
    return v;
}

// ---------------------------------------------------------------------------
// Main persistent kernel: out[N,120] = G @ M via mma.sync bf16 hi/lo split.
// Block: 256 thr = 8 warps in 2(m) x 4(n); warp tile m64 x n32.
// ---------------------------------------------------------------------------
__global__ __launch_bounds__(THREADS, 1)
void coupling_mma_kernel(const float* __restrict__ G, float* __restrict__ out,
                         int natoms, int ntiles) {
    extern __shared__ __align__(16) unsigned char smem[];
    uint32_t sbase;
    asm("{ .reg .u64 t; cvta.to.shared.u64 t, %1; cvt.u32.u64 %0, t; }"
        : "=r"(sbase) : "l"(smem));

    int tid = threadIdx.x;
    int lane = tid & 31;
    int wid = tid >> 5;
    int warp_m = wid & 1;          // 0..1
    int warp_n = wid >> 1;         // 0..3
    int m_base = warp_m * 64;
    int n_base = warp_n * 32;

    // Copy B hi/lo images to smem (once per CTA)
    {
        const uint4* bh = reinterpret_cast<const uint4*>(g_Bhi);
        const uint4* bl = reinterpret_cast<const uint4*>(g_Blo);
        uint4* sh = reinterpret_cast<uint4*>(smem + SM_B_HI);
        uint4* sl = reinterpret_cast<uint4*>(smem + SM_B_LO);
        for (int i = tid; i < AB_BYTES / 16; i += THREADS) { sh[i] = bh[i]; sl[i] = bl[i]; }
    }
    __syncthreads();

    // B_hi fragments: register-resident for the whole kernel.
    // frag (nt,kc): n = n_base+nt*8+(lane>>2), k0 = kc*16+(lane&3)*2
    uint32_t bhi[4][8][2];
    {
        int nr = n_base + (lane >> 2);
        int kb = (lane & 3) * 2;
        #pragma unroll
        for (int nt = 0; nt < 4; nt++)
            #pragma unroll
            for (int kc = 0; kc < 8; kc++) {
                uint32_t addr = sbase + SM_B_HI
                              + (uint32_t)((nr + nt * 8) * (LDAB * 2) + (kc * 16 + kb) * 2);
                bhi[nt][kc][0] = lds32(addr);
                bhi[nt][kc][1] = lds32(addr + 16u);
            }
    }

    const float4* G4 = reinterpret_cast<const float4*>(G);

    for (int tile = blockIdx.x; tile < ntiles; tile += gridDim.x) {
        int atom0 = tile * TILE_M;

        // ---- Load G tile, split bf16 hi/lo into A smem (row-major m x k) ----
        #pragma unroll 4
        for (int i = tid; i < TILE_M * 32; i += THREADS) {
            int a = i >> 5, kq = i & 31;
            int ga = atom0 + a;
            float4 v = make_float4(0.f, 0.f, 0.f, 0.f);
            if (kq < 30 && ga < natoms) v = G4[(size_t)ga * 30 + kq];

            __nv_bfloat16 hx = __float2bfloat16(v.x);
            __nv_bfloat16 hy = __float2bfloat16(v.y);
            __nv_bfloat16 hz = __float2bfloat16(v.z);
            __nv_bfloat16 hw = __float2bfloat16(v.w);
            __nv_bfloat16 lx = __float2bfloat16(v.x - __bfloat162float(hx));
            __nv_bfloat16 ly = __float2bfloat16(v.y - __bfloat162float(hy));
            __nv_bfloat16 lz = __float2bfloat16(v.z - __bfloat162float(hz));
            __nv_bfloat16 lw = __float2bfloat16(v.w - __bfloat162float(hw));

            unsigned long long hp =
                  (unsigned long long)__bfloat16_as_ushort(hx)
                | ((unsigned long long)__bfloat16_as_ushort(hy) << 16)
                | ((unsigned long long)__bfloat16_as_ushort(hz) << 32)
                | ((unsigned long long)__bfloat16_as_ushort(hw) << 48);
            unsigned long long lp =
                  (unsigned long long)__bfloat16_as_ushort(lx)
                | ((unsigned long long)__bfloat16_as_ushort(ly) << 16)
                | ((unsigned long long)__bfloat16_as_ushort(lz) << 32)
                | ((unsigned long long)__bfloat16_as_ushort(lw) << 48);

            int off = a * (LDAB * 2) + kq * 8;
            *reinterpret_cast<unsigned long long*>(smem + SM_A_HI + off) = hp;
            *reinterpret_cast<unsigned long long*>(smem + SM_A_LO + off) = lp;
        }
        __syncthreads();

        // ---- MMA mainloop ----
        float acc[4][4][4];
        #pragma unroll
        for (int mt = 0; mt < 4; mt++)
            #pragma unroll
            for (int nt = 0; nt < 4; nt++)
                #pragma unroll
                for (int q = 0; q < 4; q++) acc[mt][nt][q] = 0.f;

        // ldmatrix per-thread row/col: row = m_base + mt*16 + (lane&15),
        // kofs = kc*16 + ((lane>>4)*8)
        int lrow = m_base + (lane & 15);
        int lkof = (lane >> 4) << 3;
        int nr = n_base + (lane >> 2);
        int kb = (lane & 3) * 2;

        #pragma unroll
        for (int kc = 0; kc < 8; kc++) {
            uint32_t ahi[4][4], alo[4][4];
            #pragma unroll
            for (int mt = 0; mt < 4; mt++) {
                uint32_t aoff = (uint32_t)((lrow + mt * 16) * (LDAB * 2)
                                           + (kc * 16 + lkof) * 2);
                ldmatrix_x4(ahi[mt], sbase + SM_A_HI + aoff);
                ldmatrix_x4(alo[mt], sbase + SM_A_LO + aoff);
            }
            uint32_t blo[4][2];
            #pragma unroll
            for (int nt = 0; nt < 4; nt++) {
                uint32_t baddr = sbase + SM_B_LO
                               + (uint32_t)((nr + nt * 8) * (LDAB * 2) + (kc * 16 + kb) * 2);
                blo[nt][0] = lds32(baddr);
                blo[nt][1] = lds32(baddr + 16u);
            }
            #pragma unroll
            for (int mt = 0; mt < 4; mt++)
                #pragma unroll
                for (int nt = 0; nt < 4; nt++) {
                    mma_bf16(acc[mt][nt], ahi[mt], bhi[nt][kc]);
                    mma_bf16(acc[mt][nt], ahi[mt], blo[nt]);
                    mma_bf16(acc[mt][nt], alo[mt], bhi[nt][kc]);
                }
        }

        // ---- Store C ----
        {
            int g = lane >> 2, tg = lane & 3;
            #pragma unroll
            for (int nt = 0; nt < 4; nt++) {
                int w = n_base + nt * 8 + tg * 2;
                if (w < N_FEAT) {
                    #pragma unroll
                    for (int mt = 0; mt < 4; mt++) {
                        int r0 = atom0 + m_base + mt * 16 + g;
                        if (r0 < natoms) {
                            float2 v0 = make_float2(acc[mt][nt][0], acc[mt][nt][1]);
                            *reinterpret_cast<float2*>(out + (size_t)r0 * N_FEAT + w) = v0;
                        }
                        int r1 = r0 + 8;
                        if (r1 < natoms) {
                            float2 v1 = make_float2(acc[mt][nt][2], acc[mt][nt][3]);
                            *reinterpret_cast<float2*>(out + (size_t)r1 * N_FEAT + w) = v1;
                        }
                    }
                }
            }
        }
        __syncthreads();   // all mma reads done before next tile overwrites A
    }
}

// ---------------------------------------------------------------------------
extern "C" void kernel_launch(void* const* d_in, const int* in_sizes, int n_in,
                              void* d_out, int out_size) {
    const float* G    = (const float*)d_in[0];
    const float* f    = (const float*)d_in[1];
    const float* w000 = (const float*)d_in[2];
    const float* w011 = (const float*)d_in[3];
    const float* w101 = (const float*)d_in[4];
    const float* w110 = (const float*)d_in[5];
    const float* w112 = (const float*)d_in[6];
    const float* w202 = (const float*)d_in[7];
    const float* w211 = (const float*)d_in[8];
    const float* wl0  = (const float*)d_in[9];
    const float* wl1  = (const float*)d_in[10];
    const float* wl2  = (const float*)d_in[11];
    float* out = (float*)d_out;

    int natoms = in_sizes[0] / N_FEAT;
    int ntiles = (natoms + TILE_M - 1) / TILE_M;

    build_M_kernel<<<(N_FEAT * M_COLS + 127) / 128, 128>>>(
        f, w000, w011, w101, w110, w112, w202, w211, wl0, wl1, wl2);
    build_B_kernel<<<(128 * LDAB + 127) / 128, 128>>>();

    cudaFuncSetAttribute(coupling_mma_kernel,
                         cudaFuncAttributeMaxDynamicSharedMemorySize, SM_TOTAL);
    int grid = ntiles < GRID_CTAS ? ntiles : GRID_CTAS;
    coupling_mma_kernel<<<grid, THREADS, SM_TOTAL>>>(G, out, natoms, ntiles);
}

// round 11
// speedup vs baseline: 2.5012x; 1.3276x over previous
#include <cuda_runtime.h>
#include <cuda_bf16.h>
#include <cstdint>
#include <math.h>

#define N_FEAT 120
#define TILE_M 64
#define THREADS 256
#define GRID_CTAS 296

#define LDAB 136                     // bf16 stride (272 bytes/row)
#define A_BYTES (TILE_M * LDAB * 2)  // 17408
#define B_BYTES (128 * LDAB * 2)     // 34816

// smem offsets
#define SM_A_HI 0
#define SM_A_LO A_BYTES
#define SM_B_HI (2 * A_BYTES)
#define SM_B_LO (2 * A_BYTES + B_BYTES)
#define SM_TOTAL (2 * A_BYTES + 2 * B_BYTES)   // 104448

// Pre-built bf16 hi/lo B images: B[nrow][k] = M[k][nrow], [128][LDAB]
__device__ __align__(16) __nv_bfloat16 g_Bhi[128 * LDAB];
__device__ __align__(16) __nv_bfloat16 g_Blo[128 * LDAB];

// ---------------------------------------------------------------------------
// Fused prep: compute M[k][w] (fp32) and write transposed bf16 hi/lo B images.
// One thread per (nrow=w, k) element of the padded [128][LDAB] images.
// ---------------------------------------------------------------------------
__global__ void build_B_fused(const float* __restrict__ f,
                              const float* __restrict__ w000,
                              const float* __restrict__ w011,
                              const float* __restrict__ w101,
                              const float* __restrict__ w110,
                              const float* __restrict__ w112,
                              const float* __restrict__ w202,
                              const float* __restrict__ w211,
                              const float* __restrict__ wl0,
                              const float* __restrict__ wl1,
                              const float* __restrict__ wl2) {
    int idx = blockIdx.x * blockDim.x + threadIdx.x;
    if (idx >= 128 * LDAB) return;
    int w = idx / LDAB;     // output feature (N row)
    int k = idx % LDAB;     // input feature (K col), pad >=120 -> 0

    float val = 0.f;
    if (k < N_FEAT && w < N_FEAT) {
        // Wigner 3j (1,1,2), scaled by 1/sqrt(5)
        float Cw[3][3][5];
        #pragma unroll
        for (int a = 0; a < 3; a++)
            #pragma unroll
            for (int b = 0; b < 3; b++)
                #pragma unroll
                for (int c = 0; c < 5; c++) Cw[a][b][c] = 0.f;
        {
            float s2 = 0.7071067811865475f, s6 = 0.4082482904638631f;
            Cw[0][2][0] = s2;  Cw[2][0][0] = s2;
            Cw[0][1][1] = s2;  Cw[1][0][1] = s2;
            Cw[1][1][2] = 2.f * s6; Cw[0][0][2] = -s6; Cw[2][2][2] = -s6;
            Cw[1][2][3] = s2;  Cw[2][1][3] = s2;
            Cw[2][2][4] = s2;  Cw[0][0][4] = -s2;
            float n5 = 0.4472135954999579f;
            #pragma unroll
            for (int a = 0; a < 3; a++)
                #pragma unroll
                for (int b = 0; b < 3; b++)
                    #pragma unroll
                    for (int c = 0; c < 5; c++) Cw[a][b][c] *= n5;
        }

        const float INV_S3 = 0.5773502691896258f;
        const float INV_S5 = 0.4472135954999579f;
        const float C0v = 0.02795084971874737f;   // sqrt(1/1280)
        const float C1v = 0.05103103630798287f;   // sqrt(3/1152)
        const float C2v = 0.09882117688026186f;   // sqrt(5/512)

        if (k < 32) {
            int u = k;
            if (w < 32) {
                int wo = w;
                float s = 0.f;
                for (int v = 0; v < 32; v++) s += w000[u*1024 + v*32 + wo] * f[v];
                val = C0v * s + wl0[u*32 + wo] * 0.17677669529663687f;  // 1/sqrt(32)
            } else if (w < 80) {
                int wo = (w - 32) / 3, j = (w - 32) % 3;
                float s = 0.f;
                for (int v = 0; v < 16; v++) s += w011[u*256 + v*16 + wo] * f[32 + v*3 + j];
                val = C1v * INV_S3 * s;
            }
        } else if (k < 80) {
            int u = (k - 32) / 3, i = (k - 32) % 3;
            if (w < 32) {
                int wo = w;
                float s = 0.f;
                for (int v = 0; v < 16; v++) s += w110[u*512 + v*32 + wo] * f[32 + v*3 + i];
                val = C0v * INV_S3 * s;
            } else if (w < 80) {
                int wo = (w - 32) / 3, j = (w - 32) % 3;
                if (j == i) {
                    float s = 0.f;
                    for (int v = 0; v < 32; v++) s += w101[u*512 + v*16 + wo] * f[v];
                    val = C1v * INV_S3 * s + wl1[u*16 + wo] * 0.25f;
                }
            } else {
                int wo = (w - 80) / 5, kout = (w - 80) % 5;
                float s = 0.f;
                for (int v = 0; v < 16; v++)
                    for (int j2 = 0; j2 < 3; j2++)
                        s += w112[u*128 + v*8 + wo] * Cw[i][j2][kout] * f[32 + v*3 + j2];
                val = C2v * s;
            }
        } else {
            int u = (k - 80) / 5, i = (k - 80) % 5;
            if (w >= 32 && w < 80) {
                int wo = (w - 32) / 3, j = (w - 32) % 3;
                float s = 0.f;
                for (int v = 0; v < 16; v++)
                    for (int i2 = 0; i2 < 3; i2++)
                        s += w211[u*256 + v*16 + wo] * Cw[i2][j][i] * f[32 + v*3 + i2];
                val = C1v * s;
            } else if (w >= 80) {
                int wo = (w - 80) / 5, j = (w - 80) % 5;
                if (j == i) {
                    float s = 0.f;
                    for (int v = 0; v < 32; v++) s += w202[u*256 + v*8 + wo] * f[v];
                    val = C2v * INV_S5 * s + wl2[u*8 + wo] * 0.3535533905932738f; // 1/sqrt(8)
                }
            }
        }
    }

    __nv_bfloat16 hi = __float2bfloat16(val);
    __nv_bfloat16 lo = __float2bfloat16(val - __bfloat162float(hi));
    g_Bhi[idx] = hi;
    g_Blo[idx] = lo;
}

// ---------------------------------------------------------------------------
// mma helpers
// ---------------------------------------------------------------------------
__device__ __forceinline__ void mma_bf16(float* c, const uint32_t* a, const uint32_t* b) {
    asm volatile(
        "mma.sync.aligned.m16n8k16.row.col.f32.bf16.bf16.f32 "
        "{%0,%1,%2,%3}, {%4,%5,%6,%7}, {%8,%9}, {%0,%1,%2,%3};"
        : "+f"(c[0]), "+f"(c[1]), "+f"(c[2]), "+f"(c[3])
        : "r"(a[0]), "r"(a[1]), "r"(a[2]), "r"(a[3]), "r"(b[0]), "r"(b[1]));
}

__device__ __forceinline__ void ldmatrix_x4(uint32_t* r, uint32_t addr) {
    asm volatile("ldmatrix.sync.aligned.m8n8.x4.shared.b16 {%0,%1,%2,%3}, [%4];"
                 : "=r"(r[0]), "=r"(r[1]), "=r"(r[2]), "=r"(r[3]) : "r"(addr));
}

__device__ __forceinline__ uint32_t lds32(uint32_t addr) {
    uint32_t v;
    asm volatile("ld.shared.b32 %0, [%1];" : "=r"(v) : "r"(addr));
    return v;
}

// ---------------------------------------------------------------------------
// Main persistent kernel: out[N,120] = G @ M via mma.sync bf16 hi/lo split.
// 2 CTAs/SM for phase overlap. Block: 256 thr = 8 warps in 2(m) x 4(n);
// warp tile m32 x n32; CTA tile 64 atoms x 120 outputs.
// ---------------------------------------------------------------------------
__global__ __launch_bounds__(THREADS, 2)
void coupling_mma_kernel(const float* __restrict__ G, float* __restrict__ out,
                         int natoms, int ntiles) {
    extern __shared__ __align__(16) unsigned char smem[];
    uint32_t sbase;
    asm("{ .reg .u64 t; cvta.to.shared.u64 t, %1; cvt.u32.u64 %0, t; }"
        : "=r"(sbase) : "l"(smem));

    int tid = threadIdx.x;
    int lane = tid & 31;
    int wid = tid >> 5;
    int warp_m = wid & 1;          // 0..1
    int warp_n = wid >> 1;         // 0..3
    int m_base = warp_m * 32;
    int n_base = warp_n * 32;

    // Copy B hi/lo images to smem (once per CTA)
    {
        const uint4* bh = reinterpret_cast<const uint4*>(g_Bhi);
        const uint4* bl = reinterpret_cast<const uint4*>(g_Blo);
        uint4* sh = reinterpret_cast<uint4*>(smem + SM_B_HI);
        uint4* sl = reinterpret_cast<uint4*>(smem + SM_B_LO);
        for (int i = tid; i < B_BYTES / 16; i += THREADS) { sh[i] = bh[i]; sl[i] = bl[i]; }
    }
    __syncthreads();

    const float4* G4 = reinterpret_cast<const float4*>(G);

    // per-lane fragment coordinates
    int lrow = m_base + (lane & 15);          // ldmatrix source row (within tile)
    int lkof = (lane >> 4) << 3;              // ldmatrix k offset
    int nr = n_base + (lane >> 2);            // B fragment n row
    int kb = (lane & 3) * 2;                  // B fragment k offset

    for (int tile = blockIdx.x; tile < ntiles; tile += gridDim.x) {
        int atom0 = tile * TILE_M;

        // ---- Load G tile, split bf16 hi/lo into A smem (row-major m x k) ----
        #pragma unroll
        for (int i = tid; i < TILE_M * 32; i += THREADS) {
            int a = i >> 5, kq = i & 31;
            int ga = atom0 + a;
            float4 v = make_float4(0.f, 0.f, 0.f, 0.f);
            if (kq < 30 && ga < natoms) v = G4[(size_t)ga * 30 + kq];

            __nv_bfloat16 hx = __float2bfloat16(v.x);
            __nv_bfloat16 hy = __float2bfloat16(v.y);
            __nv_bfloat16 hz = __float2bfloat16(v.z);
            __nv_bfloat16 hw = __float2bfloat16(v.w);
            __nv_bfloat16 lx = __float2bfloat16(v.x - __bfloat162float(hx));
            __nv_bfloat16 ly = __float2bfloat16(v.y - __bfloat162float(hy));
            __nv_bfloat16 lz = __float2bfloat16(v.z - __bfloat162float(hz));
            __nv_bfloat16 lw = __float2bfloat16(v.w - __bfloat162float(hw));

            unsigned long long hp =
                  (unsigned long long)__bfloat16_as_ushort(hx)
                | ((unsigned long long)__bfloat16_as_ushort(hy) << 16)
                | ((unsigned long long)__bfloat16_as_ushort(hz) << 32)
                | ((unsigned long long)__bfloat16_as_ushort(hw) << 48);
            unsigned long long lp =
                  (unsigned long long)__bfloat16_as_ushort(lx)
                | ((unsigned long long)__bfloat16_as_ushort(ly) << 16)
                | ((unsigned long long)__bfloat16_as_ushort(lz) << 32)
                | ((unsigned long long)__bfloat16_as_ushort(lw) << 48);

            int off = a * (LDAB * 2) + kq * 8;
            *reinterpret_cast<unsigned long long*>(smem + SM_A_HI + off) = hp;
            *reinterpret_cast<unsigned long long*>(smem + SM_A_LO + off) = lp;
        }
        __syncthreads();

        // ---- MMA mainloop ----
        float acc[2][4][4];
        #pragma unroll
        for (int mt = 0; mt < 2; mt++)
            #pragma unroll
            for (int nt = 0; nt < 4; nt++)
                #pragma unroll
                for (int q = 0; q < 4; q++) acc[mt][nt][q] = 0.f;

        #pragma unroll
        for (int kc = 0; kc < 8; kc++) {
            uint32_t ahi[2][4], alo[2][4];
            #pragma unroll
            for (int mt = 0; mt < 2; mt++) {
                uint32_t aoff = (uint32_t)((lrow + mt * 16) * (LDAB * 2)
                                           + (kc * 16 + lkof) * 2);
                ldmatrix_x4(ahi[mt], sbase + SM_A_HI + aoff);
                ldmatrix_x4(alo[mt], sbase + SM_A_LO + aoff);
            }
            uint32_t bhi[4][2], blo[4][2];
            #pragma unroll
            for (int nt = 0; nt < 4; nt++) {
                uint32_t boff = (uint32_t)((nr + nt * 8) * (LDAB * 2)
                                           + (kc * 16 + kb) * 2);
                bhi[nt][0] = lds32(sbase + SM_B_HI + boff);
                bhi[nt][1] = lds32(sbase + SM_B_HI + boff + 16u);
                blo[nt][0] = lds32(sbase + SM_B_LO + boff);
                blo[nt][1] = lds32(sbase + SM_B_LO + boff + 16u);
            }
            #pragma unroll
            for (int mt = 0; mt < 2; mt++)
                #pragma unroll
                for (int nt = 0; nt < 4; nt++) {
                    mma_bf16(acc[mt][nt], ahi[mt], bhi[nt]);
                    mma_bf16(acc[mt][nt], ahi[mt], blo[nt]);
                    mma_bf16(acc[mt][nt], alo[mt], bhi[nt]);
                }
        }

        // ---- Store C ----
        {
            int g = lane >> 2, tg = lane & 3;
            #pragma unroll
            for (int nt = 0; nt < 4; nt++) {
                int w = n_base + nt * 8 + tg * 2;
                if (w < N_FEAT) {
                    #pragma unroll
                    for (int mt = 0; mt < 2; mt++) {
                        int r0 = atom0 + m_base + mt * 16 + g;
                        if (r0 < natoms) {
                            float2 v0 = make_float2(acc[mt][nt][0], acc[mt][nt][1]);
                            *reinterpret_cast<float2*>(out + (size_t)r0 * N_FEAT + w) = v0;
                        }
                        int r1 = r0 + 8;
                        if (r1 < natoms) {
                            float2 v1 = make_float2(acc[mt][nt][2], acc[mt][nt][3]);
                            *reinterpret_cast<float2*>(out + (size_t)r1 * N_FEAT + w) = v1;
                        }
                    }
                }
            }
        }
        __syncthreads();   // all mma reads done before next tile overwrites A
    }
}

// ---------------------------------------------------------------------------
extern "C" void kernel_launch(void* const* d_in, const int* in_sizes, int n_in,
                              void* d_out, int out_size) {
    const float* G    = (const float*)d_in[0];
    const float* f    = (const float*)d_in[1];
    const float* w000 = (const float*)d_in[2];
    const float* w011 = (const float*)d_in[3];
    const float* w101 = (const float*)d_in[4];
    const float* w110 = (const float*)d_in[5];
    const float* w112 = (const float*)d_in[6];
    const float* w202 = (const float*)d_in[7];
    const float* w211 = (const float*)d_in[8];
    const float* wl0  = (const float*)d_in[9];
    const float* wl1  = (const float*)d_in[10];
    const float* wl2  = (const float*)d_in[11];
    float* out = (float*)d_out;

    int natoms = in_sizes[0] / N_FEAT;
    int ntiles = (natoms + TILE_M - 1) / TILE_M;

    build_B_fused<<<(128 * LDAB + 255) / 256, 256>>>(
        f, w000, w011, w101, w110, w112, w202, w211, wl0, wl1, wl2);

    cudaFuncSetAttribute(coupling_mma_kernel,
                         cudaFuncAttributeMaxDynamicSharedMemorySize, SM_TOTAL);
    int grid = ntiles < GRID_CTAS ? ntiles : GRID_CTAS;
    coupling_mma_kernel<<<grid, THREADS, SM_TOTAL>>>(G, out, natoms, ntiles);
}

// round 12
// speedup vs baseline: 2.8924x; 1.1564x over previous
#include <cuda_runtime.h>
#include <cuda_bf16.h>
#include <cstdint>
#include <math.h>

#define N_FEAT 120
#define TILE_M 64
#define THREADS 256
#define GRID_CTAS 148

#define LDAB 136                     // bf16 stride (272 bytes/row)
#define A_IMG (TILE_M * LDAB * 2)    // 17408 bytes, one A image
#define A_BUF (2 * A_IMG)            // hi+lo for one stage = 34816
#define B_BYTES (128 * LDAB * 2)     // 34816

// smem: [A stage0 hi|lo][A stage1 hi|lo][B hi][B lo]
#define SM_B_HI (2 * A_BUF)
#define SM_B_LO (2 * A_BUF + B_BYTES)
#define SM_TOTAL (2 * A_BUF + 2 * B_BYTES)   // 139264

// Pre-built bf16 hi/lo B images: B[nrow][k] = M[k][nrow], [128][LDAB]
__device__ __align__(16) __nv_bfloat16 g_Bhi[128 * LDAB];
__device__ __align__(16) __nv_bfloat16 g_Blo[128 * LDAB];

// ---------------------------------------------------------------------------
// Fused prep: compute M[k][w] (fp32) and write transposed bf16 hi/lo B images.
// ---------------------------------------------------------------------------
__global__ void build_B_fused(const float* __restrict__ f,
                              const float* __restrict__ w000,
                              const float* __restrict__ w011,
                              const float* __restrict__ w101,
                              const float* __restrict__ w110,
                              const float* __restrict__ w112,
                              const float* __restrict__ w202,
                              const float* __restrict__ w211,
                              const float* __restrict__ wl0,
                              const float* __restrict__ wl1,
                              const float* __restrict__ wl2) {
    int idx = blockIdx.x * blockDim.x + threadIdx.x;
    if (idx >= 128 * LDAB) return;
    int w = idx / LDAB;     // output feature (N row)
    int k = idx % LDAB;     // input feature (K col), pad -> 0

    float val = 0.f;
    if (k < N_FEAT && w < N_FEAT) {
        float Cw[3][3][5];
        #pragma unroll
        for (int a = 0; a < 3; a++)
            #pragma unroll
            for (int b = 0; b < 3; b++)
                #pragma unroll
                for (int c = 0; c < 5; c++) Cw[a][b][c] = 0.f;
        {
            float s2 = 0.7071067811865475f, s6 = 0.4082482904638631f;
            Cw[0][2][0] = s2;  Cw[2][0][0] = s2;
            Cw[0][1][1] = s2;  Cw[1][0][1] = s2;
            Cw[1][1][2] = 2.f * s6; Cw[0][0][2] = -s6; Cw[2][2][2] = -s6;
            Cw[1][2][3] = s2;  Cw[2][1][3] = s2;
            Cw[2][2][4] = s2;  Cw[0][0][4] = -s2;
            float n5 = 0.4472135954999579f;
            #pragma unroll
            for (int a = 0; a < 3; a++)
                #pragma unroll
                for (int b = 0; b < 3; b++)
                    #pragma unroll
                    for (int c = 0; c < 5; c++) Cw[a][b][c] *= n5;
        }

        const float INV_S3 = 0.5773502691896258f;
        const float INV_S5 = 0.4472135954999579f;
        const float C0v = 0.02795084971874737f;   // sqrt(1/1280)
        const float C1v = 0.05103103630798287f;   // sqrt(3/1152)
        const float C2v = 0.09882117688026186f;   // sqrt(5/512)

        if (k < 32) {
            int u = k;
            if (w < 32) {
                int wo = w;
                float s = 0.f;
                for (int v = 0; v < 32; v++) s += w000[u*1024 + v*32 + wo] * f[v];
                val = C0v * s + wl0[u*32 + wo] * 0.17677669529663687f;
            } else if (w < 80) {
                int wo = (w - 32) / 3, j = (w - 32) % 3;
                float s = 0.f;
                for (int v = 0; v < 16; v++) s += w011[u*256 + v*16 + wo] * f[32 + v*3 + j];
                val = C1v * INV_S3 * s;
            }
        } else if (k < 80) {
            int u = (k - 32) / 3, i = (k - 32) % 3;
            if (w < 32) {
                int wo = w;
                float s = 0.f;
                for (int v = 0; v < 16; v++) s += w110[u*512 + v*32 + wo] * f[32 + v*3 + i];
                val = C0v * INV_S3 * s;
            } else if (w < 80) {
                int wo = (w - 32) / 3, j = (w - 32) % 3;
                if (j == i) {
                    float s = 0.f;
                    for (int v = 0; v < 32; v++) s += w101[u*512 + v*16 + wo] * f[v];
                    val = C1v * INV_S3 * s + wl1[u*16 + wo] * 0.25f;
                }
            } else {
                int wo = (w - 80) / 5, kout = (w - 80) % 5;
                float s = 0.f;
                for (int v = 0; v < 16; v++)
                    for (int j2 = 0; j2 < 3; j2++)
                        s += w112[u*128 + v*8 + wo] * Cw[i][j2][kout] * f[32 + v*3 + j2];
                val = C2v * s;
            }
        } else {
            int u = (k - 80) / 5, i = (k - 80) % 5;
            if (w >= 32 && w < 80) {
                int wo = (w - 32) / 3, j = (w - 32) % 3;
                float s = 0.f;
                for (int v = 0; v < 16; v++)
                    for (int i2 = 0; i2 < 3; i2++)
                        s += w211[u*256 + v*16 + wo] * Cw[i2][j][i] * f[32 + v*3 + i2];
                val = C1v * s;
            } else if (w >= 80) {
                int wo = (w - 80) / 5, j = (w - 80) % 5;
                if (j == i) {
                    float s = 0.f;
                    for (int v = 0; v < 32; v++) s += w202[u*256 + v*8 + wo] * f[v];
                    val = C2v * INV_S5 * s + wl2[u*8 + wo] * 0.3535533905932738f;
                }
            }
        }
    }

    __nv_bfloat16 hi = __float2bfloat16(val);
    __nv_bfloat16 lo = __float2bfloat16(val - __bfloat162float(hi));
    g_Bhi[idx] = hi;
    g_Blo[idx] = lo;
}

// ---------------------------------------------------------------------------
// mma helpers
// ---------------------------------------------------------------------------
__device__ __forceinline__ void mma_bf16(float* c, const uint32_t* a, const uint32_t* b) {
    asm volatile(
        "mma.sync.aligned.m16n8k16.row.col.f32.bf16.bf16.f32 "
        "{%0,%1,%2,%3}, {%4,%5,%6,%7}, {%8,%9}, {%0,%1,%2,%3};"
        : "+f"(c[0]), "+f"(c[1]), "+f"(c[2]), "+f"(c[3])
        : "r"(a[0]), "r"(a[1]), "r"(a[2]), "r"(a[3]), "r"(b[0]), "r"(b[1]));
}

__device__ __forceinline__ void ldmatrix_x4(uint32_t* r, uint32_t addr) {
    asm volatile("ldmatrix.sync.aligned.m8n8.x4.shared.b16 {%0,%1,%2,%3}, [%4];"
                 : "=r"(r[0]), "=r"(r[1]), "=r"(r[2]), "=r"(r[3]) : "r"(addr));
}

__device__ __forceinline__ uint32_t lds32(uint32_t addr) {
    uint32_t v;
    asm volatile("ld.shared.b32 %0, [%1];" : "=r"(v) : "r"(addr));
    return v;
}

// ---------------------------------------------------------------------------
// Tile load helpers: LDG into registers (issued early), STS+convert (late).
// i = tid + j*256 indexes (a = i>>5 atom row, kq = i&31 float4 k-group).
// ---------------------------------------------------------------------------
__device__ __forceinline__ void ldg_tile(const float4* __restrict__ G4, float4* v,
                                         int atom0, int natoms, int tid) {
    #pragma unroll
    for (int j = 0; j < 8; j++) {
        int i = tid + j * THREADS;
        int a = i >> 5, kq = i & 31;
        int ga = atom0 + a;
        float4 t = make_float4(0.f, 0.f, 0.f, 0.f);
        if (kq < 30 && ga < natoms) t = G4[(size_t)ga * 30 + kq];
        v[j] = t;
    }
}

__device__ __forceinline__ void sts_tile(unsigned char* smem, int bufoff,
                                         const float4* v, int tid) {
    #pragma unroll
    for (int j = 0; j < 8; j++) {
        int i = tid + j * THREADS;
        int a = i >> 5, kq = i & 31;
        float4 t = v[j];

        __nv_bfloat16 hx = __float2bfloat16(t.x);
        __nv_bfloat16 hy = __float2bfloat16(t.y);
        __nv_bfloat16 hz = __float2bfloat16(t.z);
        __nv_bfloat16 hw = __float2bfloat16(t.w);
        __nv_bfloat16 lx = __float2bfloat16(t.x - __bfloat162float(hx));
        __nv_bfloat16 ly = __float2bfloat16(t.y - __bfloat162float(hy));
        __nv_bfloat16 lz = __float2bfloat16(t.z - __bfloat162float(hz));
        __nv_bfloat16 lw = __float2bfloat16(t.w - __bfloat162float(hw));

        unsigned long long hp =
              (unsigned long long)__bfloat16_as_ushort(hx)
            | ((unsigned long long)__bfloat16_as_ushort(hy) << 16)
            | ((unsigned long long)__bfloat16_as_ushort(hz) << 32)
            | ((unsigned long long)__bfloat16_as_ushort(hw) << 48);
        unsigned long long lp =
              (unsigned long long)__bfloat16_as_ushort(lx)
            | ((unsigned long long)__bfloat16_as_ushort(ly) << 16)
            | ((unsigned long long)__bfloat16_as_ushort(lz) << 32)
            | ((unsigned long long)__bfloat16_as_ushort(lw) << 48);

        int off = a * (LDAB * 2) + kq * 8;
        *reinterpret_cast<unsigned long long*>(smem + bufoff + off) = hp;
        *reinterpret_cast<unsigned long long*>(smem + bufoff + A_IMG + off) = lp;
    }
}

// ---------------------------------------------------------------------------
// Main persistent kernel: out[N,120] = G @ M via mma.sync bf16 hi/lo split.
// 1 CTA/SM, double-buffered A, explicit LDG prefetch overlapped with MMA.
// Block: 256 thr = 8 warps in 2(m) x 4(n); warp tile m32 x n32.
// ---------------------------------------------------------------------------
__global__ __launch_bounds__(THREADS, 1)
void coupling_mma_kernel(const float* __restrict__ G, float* __restrict__ out,
                         int natoms, int ntiles) {
    extern __shared__ __align__(16) unsigned char smem[];
    uint32_t sbase;
    asm("{ .reg .u64 t; cvta.to.shared.u64 t, %1; cvt.u32.u64 %0, t; }"
        : "=r"(sbase) : "l"(smem));

    int tid = threadIdx.x;
    int lane = tid & 31;
    int wid = tid >> 5;
    int warp_m = wid & 1;
    int warp_n = wid >> 1;
    int m_base = warp_m * 32;
    int n_base = warp_n * 32;

    // Copy B hi/lo images to smem (once per CTA)
    {
        const uint4* bh = reinterpret_cast<const uint4*>(g_Bhi);
        const uint4* bl = reinterpret_cast<const uint4*>(g_Blo);
        uint4* sh = reinterpret_cast<uint4*>(smem + SM_B_HI);
        uint4* sl = reinterpret_cast<uint4*>(smem + SM_B_LO);
        for (int i = tid; i < B_BYTES / 16; i += THREADS) { sh[i] = bh[i]; sl[i] = bl[i]; }
    }

    const float4* G4 = reinterpret_cast<const float4*>(G);

    // per-lane fragment coordinates
    int lrow = m_base + (lane & 15);
    int lkof = (lane >> 4) << 3;
    int nr = n_base + (lane >> 2);
    int kb = (lane & 3) * 2;

    float4 v[8];
    int tile = blockIdx.x;

    // Prologue: fill stage 0
    if (tile < ntiles) {
        ldg_tile(G4, v, tile * TILE_M, natoms, tid);
        sts_tile(smem, 0, v, tid);
    }
    __syncthreads();

    int it = 0;
    for (; tile < ntiles; tile += gridDim.x) {
        int atom0 = tile * TILE_M;
        int ntile = tile + gridDim.x;

        // 1) Prefetch next tile's G into registers (LDGs issue now, consumed late)
        if (ntile < ntiles) ldg_tile(G4, v, ntile * TILE_M, natoms, tid);

        // 2) MMA mainloop on current stage
        int AH = it * A_BUF;
        int AL = AH + A_IMG;

        float acc[2][4][4];
        #pragma unroll
        for (int mt = 0; mt < 2; mt++)
            #pragma unroll
            for (int nt = 0; nt < 4; nt++)
                #pragma unroll
                for (int q = 0; q < 4; q++) acc[mt][nt][q] = 0.f;

        #pragma unroll
        for (int kc = 0; kc < 8; kc++) {
            uint32_t ahi[2][4], alo[2][4];
            #pragma unroll
            for (int mt = 0; mt < 2; mt++) {
                uint32_t aoff = (uint32_t)((lrow + mt * 16) * (LDAB * 2)
                                           + (kc * 16 + lkof) * 2);
                ldmatrix_x4(ahi[mt], sbase + AH + aoff);
                ldmatrix_x4(alo[mt], sbase + AL + aoff);
            }
            uint32_t bhi[4][2], blo[4][2];
            #pragma unroll
            for (int nt = 0; nt < 4; nt++) {
                uint32_t boff = (uint32_t)((nr + nt * 8) * (LDAB * 2)
                                           + (kc * 16 + kb) * 2);
                bhi[nt][0] = lds32(sbase + SM_B_HI + boff);
                bhi[nt][1] = lds32(sbase + SM_B_HI + boff + 16u);
                blo[nt][0] = lds32(sbase + SM_B_LO + boff);
                blo[nt][1] = lds32(sbase + SM_B_LO + boff + 16u);
            }
            #pragma unroll
            for (int mt = 0; mt < 2; mt++)
                #pragma unroll
                for (int nt = 0; nt < 4; nt++) {
                    mma_bf16(acc[mt][nt], ahi[mt], bhi[nt]);
                    mma_bf16(acc[mt][nt], ahi[mt], blo[nt]);
                    mma_bf16(acc[mt][nt], alo[mt], bhi[nt]);
                }
        }

        // 3) Convert + store prefetched G into the other stage
        if (ntile < ntiles) sts_tile(smem, (it ^ 1) * A_BUF, v, tid);

        // 4) Store C
        {
            int g = lane >> 2, tg = lane & 3;
            #pragma unroll
            for (int nt = 0; nt < 4; nt++) {
                int w = n_base + nt * 8 + tg * 2;
                if (w < N_FEAT) {
                    #pragma unroll
                    for (int mt = 0; mt < 2; mt++) {
                        int r0 = atom0 + m_base + mt * 16 + g;
                        if (r0 < natoms) {
                            float2 v0 = make_float2(acc[mt][nt][0], acc[mt][nt][1]);
                            *reinterpret_cast<float2*>(out + (size_t)r0 * N_FEAT + w) = v0;
                        }
                        int r1 = r0 + 8;
                        if (r1 < natoms) {
                            float2 v1 = make_float2(acc[mt][nt][2], acc[mt][nt][3]);
                            *reinterpret_cast<float2*>(out + (size_t)r1 * N_FEAT + w) = v1;
                        }
                    }
                }
            }
        }

        __syncthreads();   // stage it consumed by all; stage it^1 fully written
        it ^= 1;
    }
}

// ---------------------------------------------------------------------------
extern "C" void kernel_launch(void* const* d_in, const int* in_sizes, int n_in,
                              void* d_out, int out_size) {
    const float* G    = (const float*)d_in[0];
    const float* f    = (const float*)d_in[1];
    const float* w000 = (const float*)d_in[2];
    const float* w011 = (const float*)d_in[3];
    const float* w101 = (const float*)d_in[4];
    const float* w110 = (const float*)d_in[5];
    const float* w112 = (const float*)d_in[6];
    const float* w202 = (const float*)d_in[7];
    const float* w211 = (const float*)d_in[8];
    const float* wl0  = (const float*)d_in[9];
    const float* wl1  = (const float*)d_in[10];
    const float* wl2  = (const float*)d_in[11];
    float* out = (float*)d_out;

    int natoms = in_sizes[0] / N_FEAT;
    int ntiles = (natoms + TILE_M - 1) / TILE_M;

    build_B_fused<<<(128 * LDAB + 255) / 256, 256>>>(
        f, w000, w011, w101, w110, w112, w202, w211, wl0, wl1, wl2);

    cudaFuncSetAttribute(coupling_mma_kernel,
                         cudaFuncAttributeMaxDynamicSharedMemorySize, SM_TOTAL);
    int grid = ntiles < GRID_CTAS ? ntiles : GRID_CTAS;
    coupling_mma_kernel<<<grid, THREADS, SM_TOTAL>>>(G, out, natoms, ntiles);
}

// round 13
// speedup vs baseline: 2.9190x; 1.0092x over previous
#include <cuda_runtime.h>
#include <cuda_bf16.h>
#include <cstdint>
#include <math.h>

#define N_FEAT 120
#define TILE_M 96
#define THREADS 384
#define GRID_CTAS 148

#define LDAB 136                     // bf16 stride (272 bytes/row)
#define A_IMG (TILE_M * LDAB * 2)    // 26112 bytes, one A image
#define A_BUF (2 * A_IMG)            // hi+lo for one stage = 52224
#define B_BYTES (128 * LDAB * 2)     // 34816

// smem: [A stage0 hi|lo][A stage1 hi|lo][B hi][B lo]
#define SM_B_HI (2 * A_BUF)
#define SM_B_LO (2 * A_BUF + B_BYTES)
#define SM_TOTAL (2 * A_BUF + 2 * B_BYTES)   // 174080

// Pre-built bf16 hi/lo B images: B[nrow][k] = M[k][nrow], [128][LDAB]
__device__ __align__(16) __nv_bfloat16 g_Bhi[128 * LDAB];
__device__ __align__(16) __nv_bfloat16 g_Blo[128 * LDAB];

// ---------------------------------------------------------------------------
// Fused prep: compute M[k][w] (fp32) and write transposed bf16 hi/lo B images.
// ---------------------------------------------------------------------------
__global__ void build_B_fused(const float* __restrict__ f,
                              const float* __restrict__ w000,
                              const float* __restrict__ w011,
                              const float* __restrict__ w101,
                              const float* __restrict__ w110,
                              const float* __restrict__ w112,
                              const float* __restrict__ w202,
                              const float* __restrict__ w211,
                              const float* __restrict__ wl0,
                              const float* __restrict__ wl1,
                              const float* __restrict__ wl2) {
    int idx = blockIdx.x * blockDim.x + threadIdx.x;
    if (idx >= 128 * LDAB) return;
    int w = idx / LDAB;     // output feature (N row)
    int k = idx % LDAB;     // input feature (K col), pad -> 0

    float val = 0.f;
    if (k < N_FEAT && w < N_FEAT) {
        float Cw[3][3][5];
        #pragma unroll
        for (int a = 0; a < 3; a++)
            #pragma unroll
            for (int b = 0; b < 3; b++)
                #pragma unroll
                for (int c = 0; c < 5; c++) Cw[a][b][c] = 0.f;
        {
            float s2 = 0.7071067811865475f, s6 = 0.4082482904638631f;
            Cw[0][2][0] = s2;  Cw[2][0][0] = s2;
            Cw[0][1][1] = s2;  Cw[1][0][1] = s2;
            Cw[1][1][2] = 2.f * s6; Cw[0][0][2] = -s6; Cw[2][2][2] = -s6;
            Cw[1][2][3] = s2;  Cw[2][1][3] = s2;
            Cw[2][2][4] = s2;  Cw[0][0][4] = -s2;
            float n5 = 0.4472135954999579f;
            #pragma unroll
            for (int a = 0; a < 3; a++)
                #pragma unroll
                for (int b = 0; b < 3; b++)
                    #pragma unroll
                    for (int c = 0; c < 5; c++) Cw[a][b][c] *= n5;
        }

        const float INV_S3 = 0.5773502691896258f;
        const float INV_S5 = 0.4472135954999579f;
        const float C0v = 0.02795084971874737f;   // sqrt(1/1280)
        const float C1v = 0.05103103630798287f;   // sqrt(3/1152)
        const float C2v = 0.09882117688026186f;   // sqrt(5/512)

        if (k < 32) {
            int u = k;
            if (w < 32) {
                int wo = w;
                float s = 0.f;
                for (int v = 0; v < 32; v++) s += w000[u*1024 + v*32 + wo] * f[v];
                val = C0v * s + wl0[u*32 + wo] * 0.17677669529663687f;
            } else if (w < 80) {
                int wo = (w - 32) / 3, j = (w - 32) % 3;
                float s = 0.f;
                for (int v = 0; v < 16; v++) s += w011[u*256 + v*16 + wo] * f[32 + v*3 + j];
                val = C1v * INV_S3 * s;
            }
        } else if (k < 80) {
            int u = (k - 32) / 3, i = (k - 32) % 3;
            if (w < 32) {
                int wo = w;
                float s = 0.f;
                for (int v = 0; v < 16; v++) s += w110[u*512 + v*32 + wo] * f[32 + v*3 + i];
                val = C0v * INV_S3 * s;
            } else if (w < 80) {
                int wo = (w - 32) / 3, j = (w - 32) % 3;
                if (j == i) {
                    float s = 0.f;
                    for (int v = 0; v < 32; v++) s += w101[u*512 + v*16 + wo] * f[v];
                    val = C1v * INV_S3 * s + wl1[u*16 + wo] * 0.25f;
                }
            } else {
                int wo = (w - 80) / 5, kout = (w - 80) % 5;
                float s = 0.f;
                for (int v = 0; v < 16; v++)
                    for (int j2 = 0; j2 < 3; j2++)
                        s += w112[u*128 + v*8 + wo] * Cw[i][j2][kout] * f[32 + v*3 + j2];
                val = C2v * s;
            }
        } else {
            int u = (k - 80) / 5, i = (k - 80) % 5;
            if (w >= 32 && w < 80) {
                int wo = (w - 32) / 3, j = (w - 32) % 3;
                float s = 0.f;
                for (int v = 0; v < 16; v++)
                    for (int i2 = 0; i2 < 3; i2++)
                        s += w211[u*256 + v*16 + wo] * Cw[i2][j][i] * f[32 + v*3 + i2];
                val = C1v * s;
            } else if (w >= 80) {
                int wo = (w - 80) / 5, j = (w - 80) % 5;
                if (j == i) {
                    float s = 0.f;
                    for (int v = 0; v < 32; v++) s += w202[u*256 + v*8 + wo] * f[v];
                    val = C2v * INV_S5 * s + wl2[u*8 + wo] * 0.3535533905932738f;
                }
            }
        }
    }

    __nv_bfloat16 hi = __float2bfloat16(val);
    __nv_bfloat16 lo = __float2bfloat16(val - __bfloat162float(hi));
    g_Bhi[idx] = hi;
    g_Blo[idx] = lo;
}

// ---------------------------------------------------------------------------
// mma helpers
// ---------------------------------------------------------------------------
__device__ __forceinline__ void mma_bf16(float* c, const uint32_t* a, const uint32_t* b) {
    asm volatile(
        "mma.sync.aligned.m16n8k16.row.col.f32.bf16.bf16.f32 "
        "{%0,%1,%2,%3}, {%4,%5,%6,%7}, {%8,%9}, {%0,%1,%2,%3};"
        : "+f"(c[0]), "+f"(c[1]), "+f"(c[2]), "+f"(c[3])
        : "r"(a[0]), "r"(a[1]), "r"(a[2]), "r"(a[3]), "r"(b[0]), "r"(b[1]));
}

__device__ __forceinline__ void ldmatrix_x4(uint32_t* r, uint32_t addr) {
    asm volatile("ldmatrix.sync.aligned.m8n8.x4.shared.b16 {%0,%1,%2,%3}, [%4];"
                 : "=r"(r[0]), "=r"(r[1]), "=r"(r[2]), "=r"(r[3]) : "r"(addr));
}

__device__ __forceinline__ uint32_t lds32(uint32_t addr) {
    uint32_t v;
    asm volatile("ld.shared.b32 %0, [%1];" : "=r"(v) : "r"(addr));
    return v;
}

// ---------------------------------------------------------------------------
// Tile load helpers: LDG into registers (issued early), STS+convert (late).
// i = tid + j*THREADS indexes (a = i>>5 atom row, kq = i&31 float4 k-group).
// TILE_M*32 = 3072 slots = 8 * 384 exactly.
// ---------------------------------------------------------------------------
__device__ __forceinline__ void ldg_tile(const float4* __restrict__ G4, float4* v,
                                         int atom0, int natoms, int tid) {
    #pragma unroll
    for (int j = 0; j < 8; j++) {
        int i = tid + j * THREADS;
        int a = i >> 5, kq = i & 31;
        int ga = atom0 + a;
        float4 t = make_float4(0.f, 0.f, 0.f, 0.f);
        if (kq < 30 && ga < natoms) t = G4[(size_t)ga * 30 + kq];
        v[j] = t;
    }
}

__device__ __forceinline__ void sts_tile(unsigned char* smem, int bufoff,
                                         const float4* v, int tid) {
    #pragma unroll
    for (int j = 0; j < 8; j++) {
        int i = tid + j * THREADS;
        int a = i >> 5, kq = i & 31;
        float4 t = v[j];

        __nv_bfloat16 hx = __float2bfloat16(t.x);
        __nv_bfloat16 hy = __float2bfloat16(t.y);
        __nv_bfloat16 hz = __float2bfloat16(t.z);
        __nv_bfloat16 hw = __float2bfloat16(t.w);
        __nv_bfloat16 lx = __float2bfloat16(t.x - __bfloat162float(hx));
        __nv_bfloat16 ly = __float2bfloat16(t.y - __bfloat162float(hy));
        __nv_bfloat16 lz = __float2bfloat16(t.z - __bfloat162float(hz));
        __nv_bfloat16 lw = __float2bfloat16(t.w - __bfloat162float(hw));

        unsigned long long hp =
              (unsigned long long)__bfloat16_as_ushort(hx)
            | ((unsigned long long)__bfloat16_as_ushort(hy) << 16)
            | ((unsigned long long)__bfloat16_as_ushort(hz) << 32)
            | ((unsigned long long)__bfloat16_as_ushort(hw) << 48);
        unsigned long long lp =
              (unsigned long long)__bfloat16_as_ushort(lx)
            | ((unsigned long long)__bfloat16_as_ushort(ly) << 16)
            | ((unsigned long long)__bfloat16_as_ushort(lz) << 32)
            | ((unsigned long long)__bfloat16_as_ushort(lw) << 48);

        int off = a * (LDAB * 2) + kq * 8;
        *reinterpret_cast<unsigned long long*>(smem + bufoff + off) = hp;
        *reinterpret_cast<unsigned long long*>(smem + bufoff + A_IMG + off) = lp;
    }
}

// ---------------------------------------------------------------------------
// Main persistent kernel: out[N,120] = G @ M via mma.sync bf16 hi/lo split.
// 1 CTA/SM, 12 warps (3 m-groups x 4 n-groups), warp tile m32 x n32,
// double-buffered A with register LDG prefetch.
// ---------------------------------------------------------------------------
__global__ __launch_bounds__(THREADS, 1)
void coupling_mma_kernel(const float* __restrict__ G, float* __restrict__ out,
                         int natoms, int ntiles) {
    extern __shared__ __align__(16) unsigned char smem[];
    uint32_t sbase;
    asm("{ .reg .u64 t; cvta.to.shared.u64 t, %1; cvt.u32.u64 %0, t; }"
        : "=r"(sbase) : "l"(smem));

    int tid = threadIdx.x;
    int lane = tid & 31;
    int wid = tid >> 5;            // 0..11
    int warp_m = wid % 3;          // 0..2  -> 96 atoms
    int warp_n = wid / 3;          // 0..3  -> 128 cols
    int m_base = warp_m * 32;
    int n_base = warp_n * 32;

    // Copy B hi/lo images to smem (once per CTA)
    {
        const uint4* bh = reinterpret_cast<const uint4*>(g_Bhi);
        const uint4* bl = reinterpret_cast<const uint4*>(g_Blo);
        uint4* sh = reinterpret_cast<uint4*>(smem + SM_B_HI);
        uint4* sl = reinterpret_cast<uint4*>(smem + SM_B_LO);
        for (int i = tid; i < B_BYTES / 16; i += THREADS) { sh[i] = bh[i]; sl[i] = bl[i]; }
    }

    const float4* G4 = reinterpret_cast<const float4*>(G);

    // per-lane fragment coordinates
    int lrow = m_base + (lane & 15);
    int lkof = (lane >> 4) << 3;
    int nr = n_base + (lane >> 2);
    int kb = (lane & 3) * 2;

    float4 v[8];
    int tile = blockIdx.x;

    // Prologue: fill stage 0
    if (tile < ntiles) {
        ldg_tile(G4, v, tile * TILE_M, natoms, tid);
        sts_tile(smem, 0, v, tid);
    }
    __syncthreads();

    int it = 0;
    for (; tile < ntiles; tile += gridDim.x) {
        int atom0 = tile * TILE_M;
        int ntile = tile + gridDim.x;

        // 1) Prefetch next tile's G into registers
        if (ntile < ntiles) ldg_tile(G4, v, ntile * TILE_M, natoms, tid);

        // 2) MMA mainloop on current stage
        int AH = it * A_BUF;
        int AL = AH + A_IMG;

        float acc[2][4][4];
        #pragma unroll
        for (int mt = 0; mt < 2; mt++)
            #pragma unroll
            for (int nt = 0; nt < 4; nt++)
                #pragma unroll
                for (int q = 0; q < 4; q++) acc[mt][nt][q] = 0.f;

        #pragma unroll
        for (int kc = 0; kc < 8; kc++) {
            uint32_t ahi[2][4], alo[2][4];
            #pragma unroll
            for (int mt = 0; mt < 2; mt++) {
                uint32_t aoff = (uint32_t)((lrow + mt * 16) * (LDAB * 2)
                                           + (kc * 16 + lkof) * 2);
                ldmatrix_x4(ahi[mt], sbase + AH + aoff);
                ldmatrix_x4(alo[mt], sbase + AL + aoff);
            }
            uint32_t bhi[4][2], blo[4][2];
            #pragma unroll
            for (int nt = 0; nt < 4; nt++) {
                uint32_t boff = (uint32_t)((nr + nt * 8) * (LDAB * 2)
                                           + (kc * 16 + kb) * 2);
                bhi[nt][0] = lds32(sbase + SM_B_HI + boff);
                bhi[nt][1] = lds32(sbase + SM_B_HI + boff + 16u);
                blo[nt][0] = lds32(sbase + SM_B_LO + boff);
                blo[nt][1] = lds32(sbase + SM_B_LO + boff + 16u);
            }
            #pragma unroll
            for (int mt = 0; mt < 2; mt++)
                #pragma unroll
                for (int nt = 0; nt < 4; nt++) {
                    mma_bf16(acc[mt][nt], ahi[mt], bhi[nt]);
                    mma_bf16(acc[mt][nt], ahi[mt], blo[nt]);
                    mma_bf16(acc[mt][nt], alo[mt], bhi[nt]);
                }
        }

        // 3) Convert + store prefetched G into the other stage
        if (ntile < ntiles) sts_tile(smem, (it ^ 1) * A_BUF, v, tid);

        // 4) Store C
        {
            int g = lane >> 2, tg = lane & 3;
            #pragma unroll
            for (int nt = 0; nt < 4; nt++) {
                int w = n_base + nt * 8 + tg * 2;
                if (w < N_FEAT) {
                    #pragma unroll
                    for (int mt = 0; mt < 2; mt++) {
                        int r0 = atom0 + m_base + mt * 16 + g;
                        if (r0 < natoms) {
                            float2 v0 = make_float2(acc[mt][nt][0], acc[mt][nt][1]);
                            *reinterpret_cast<float2*>(out + (size_t)r0 * N_FEAT + w) = v0;
                        }
                        int r1 = r0 + 8;
                        if (r1 < natoms) {
                            float2 v1 = make_float2(acc[mt][nt][2], acc[mt][nt][3]);
                            *reinterpret_cast<float2*>(out + (size_t)r1 * N_FEAT + w) = v1;
                        }
                    }
                }
            }
        }

        __syncthreads();   // stage it consumed by all; stage it^1 fully written
        it ^= 1;
    }
}

// ---------------------------------------------------------------------------
extern "C" void kernel_launch(void* const* d_in, const int* in_sizes, int n_in,
                              void* d_out, int out_size) {
    const float* G    = (const float*)d_in[0];
    const float* f    = (const float*)d_in[1];
    const float* w000 = (const float*)d_in[2];
    const float* w011 = (const float*)d_in[3];
    const float* w101 = (const float*)d_in[4];
    const float* w110 = (const float*)d_in[5];
    const float* w112 = (const float*)d_in[6];
    const float* w202 = (const float*)d_in[7];
    const float* w211 = (const float*)d_in[8];
    const float* wl0  = (const float*)d_in[9];
    const float* wl1  = (const float*)d_in[10];
    const float* wl2  = (const float*)d_in[11];
    float* out = (float*)d_out;

    int natoms = in_sizes[0] / N_FEAT;
    int ntiles = (natoms + TILE_M - 1) / TILE_M;

    build_B_fused<<<(128 * LDAB + 255) / 256, 256>>>(
        f, w000, w011, w101, w110, w112, w202, w211, wl0, wl1, wl2);

    cudaFuncSetAttribute(coupling_mma_kernel,
                         cudaFuncAttributeMaxDynamicSharedMemorySize, SM_TOTAL);
    int grid = ntiles < GRID_CTAS ? ntiles : GRID_CTAS;
    coupling_mma_kernel<<<grid, THREADS, SM_TOTAL>>>(G, out, natoms, ntiles);
}

// round 15
// speedup vs baseline: 2.9207x; 1.0006x over previous
#include <cuda_runtime.h>
#include <cuda_bf16.h>
#include <cstdint>
#include <math.h>

#define N_FEAT 120
#define TILE_M 64
#define THREADS 256
#define GRID_CTAS 148

#define LDAB 136                     // bf16 stride (272 bytes/row)
#define A_IMG (TILE_M * LDAB * 2)    // 17408 bytes, one A image
#define A_BUF (2 * A_IMG)            // hi+lo for one stage = 34816
#define B_BYTES (128 * LDAB * 2)     // 34816

// smem: [A stage0 hi|lo][A stage1 hi|lo][B hi][B lo]
#define SM_B_HI (2 * A_BUF)
#define SM_B_LO (2 * A_BUF + B_BYTES)
#define SM_TOTAL (2 * A_BUF + 2 * B_BYTES)   // 139264

// Pre-built bf16 hi/lo B images: B[nrow][k] = M[k][nrow], [128][LDAB]
__device__ __align__(16) __nv_bfloat16 g_Bhi[128 * LDAB];
__device__ __align__(16) __nv_bfloat16 g_Blo[128 * LDAB];

// ---------------------------------------------------------------------------
// Fused prep: compute M[k][w] (fp32) and write transposed bf16 hi/lo B images.
// ---------------------------------------------------------------------------
__global__ void build_B_fused(const float* __restrict__ f,
                              const float* __restrict__ w000,
                              const float* __restrict__ w011,
                              const float* __restrict__ w101,
                              const float* __restrict__ w110,
                              const float* __restrict__ w112,
                              const float* __restrict__ w202,
                              const float* __restrict__ w211,
                              const float* __restrict__ wl0,
                              const float* __restrict__ wl1,
                              const float* __restrict__ wl2) {
    int idx = blockIdx.x * blockDim.x + threadIdx.x;
    if (idx >= 128 * LDAB) return;
    int w = idx / LDAB;     // output feature (N row)
    int k = idx % LDAB;     // input feature (K col), pad -> 0

    float val = 0.f;
    if (k < N_FEAT && w < N_FEAT) {
        float Cw[3][3][5];
        #pragma unroll
        for (int a = 0; a < 3; a++)
            #pragma unroll
            for (int b = 0; b < 3; b++)
                #pragma unroll
                for (int c = 0; c < 5; c++) Cw[a][b][c] = 0.f;
        {
            float s2 = 0.7071067811865475f, s6 = 0.4082482904638631f;
            Cw[0][2][0] = s2;  Cw[2][0][0] = s2;
            Cw[0][1][1] = s2;  Cw[1][0][1] = s2;
            Cw[1][1][2] = 2.f * s6; Cw[0][0][2] = -s6; Cw[2][2][2] = -s6;
            Cw[1][2][3] = s2;  Cw[2][1][3] = s2;
            Cw[2][2][4] = s2;  Cw[0][0][4] = -s2;
            float n5 = 0.4472135954999579f;
            #pragma unroll
            for (int a = 0; a < 3; a++)
                #pragma unroll
                for (int b = 0; b < 3; b++)
                    #pragma unroll
                    for (int c = 0; c < 5; c++) Cw[a][b][c] *= n5;
        }

        const float INV_S3 = 0.5773502691896258f;
        const float INV_S5 = 0.4472135954999579f;
        const float C0v = 0.02795084971874737f;   // sqrt(1/1280)
        const float C1v = 0.05103103630798287f;   // sqrt(3/1152)
        const float C2v = 0.09882117688026186f;   // sqrt(5/512)

        if (k < 32) {
            int u = k;
            if (w < 32) {
                int wo = w;
                float s = 0.f;
                for (int v = 0; v < 32; v++) s += w000[u*1024 + v*32 + wo] * f[v];
                val = C0v * s + wl0[u*32 + wo] * 0.17677669529663687f;
            } else if (w < 80) {
                int wo = (w - 32) / 3, j = (w - 32) % 3;
                float s = 0.f;
                for (int v = 0; v < 16; v++) s += w011[u*256 + v*16 + wo] * f[32 + v*3 + j];
                val = C1v * INV_S3 * s;
            }
        } else if (k < 80) {
            int u = (k - 32) / 3, i = (k - 32) % 3;
            if (w < 32) {
                int wo = w;
                float s = 0.f;
                for (int v = 0; v < 16; v++) s += w110[u*512 + v*32 + wo] * f[32 + v*3 + i];
                val = C0v * INV_S3 * s;
            } else if (w < 80) {
                int wo = (w - 32) / 3, j = (w - 32) % 3;
                if (j == i) {
                    float s = 0.f;
                    for (int v = 0; v < 32; v++) s += w101[u*512 + v*16 + wo] * f[v];
                    val = C1v * INV_S3 * s + wl1[u*16 + wo] * 0.25f;
                }
            } else {
                int wo = (w - 80) / 5, kout = (w - 80) % 5;
                float s = 0.f;
                for (int v = 0; v < 16; v++)
                    for (int j2 = 0; j2 < 3; j2++)
                        s += w112[u*128 + v*8 + wo] * Cw[i][j2][kout] * f[32 + v*3 + j2];
                val = C2v * s;
            }
        } else {
            int u = (k - 80) / 5, i = (k - 80) % 5;
            if (w >= 32 && w < 80) {
                int wo = (w - 32) / 3, j = (w - 32) % 3;
                float s = 0.f;
                for (int v = 0; v < 16; v++)
                    for (int i2 = 0; i2 < 3; i2++)
                        s += w211[u*256 + v*16 + wo] * Cw[i2][j][i] * f[32 + v*3 + i2];
                val = C1v * s;
            } else if (w >= 80) {
                int wo = (w - 80) / 5, j = (w - 80) % 5;
                if (j == i) {
                    float s = 0.f;
                    for (int v = 0; v < 32; v++) s += w202[u*256 + v*8 + wo] * f[v];
                    val = C2v * INV_S5 * s + wl2[u*8 + wo] * 0.3535533905932738f;
                }
            }
        }
    }

    __nv_bfloat16 hi = __float2bfloat16(val);
    __nv_bfloat16 lo = __float2bfloat16(val - __bfloat162float(hi));
    g_Bhi[idx] = hi;
    g_Blo[idx] = lo;
}

// ---------------------------------------------------------------------------
// mma helpers
// ---------------------------------------------------------------------------
__device__ __forceinline__ void mma_bf16(float* c, const uint32_t* a, const uint32_t* b) {
    asm volatile(
        "mma.sync.aligned.m16n8k16.row.col.f32.bf16.bf16.f32 "
        "{%0,%1,%2,%3}, {%4,%5,%6,%7}, {%8,%9}, {%0,%1,%2,%3};"
        : "+f"(c[0]), "+f"(c[1]), "+f"(c[2]), "+f"(c[3])
        : "r"(a[0]), "r"(a[1]), "r"(a[2]), "r"(a[3]), "r"(b[0]), "r"(b[1]));
}

__device__ __forceinline__ void ldmatrix_x4(uint32_t* r, uint32_t addr) {
    asm volatile("ldmatrix.sync.aligned.m8n8.x4.shared.b16 {%0,%1,%2,%3}, [%4];"
                 : "=r"(r[0]), "=r"(r[1]), "=r"(r[2]), "=r"(r[3]) : "r"(addr));
}

__device__ __forceinline__ uint32_t lds32(uint32_t addr) {
    uint32_t v;
    asm volatile("ld.shared.b32 %0, [%1];" : "=r"(v) : "r"(addr));
    return v;
}

// Fragment set for one kc step
struct Frags {
    uint32_t ahi[2][4];
    uint32_t alo[2][4];
    uint32_t bhi[4][2];
    uint32_t blo[4][2];
};

__device__ __forceinline__ void load_frags(Frags& fr, uint32_t sbase, int AH, int AL,
                                           int kc, int lrow, int lkof, int nr, int kb) {
    #pragma unroll
    for (int mt = 0; mt < 2; mt++) {
        uint32_t aoff = (uint32_t)((lrow + mt * 16) * (LDAB * 2) + (kc * 16 + lkof) * 2);
        ldmatrix_x4(fr.ahi[mt], sbase + AH + aoff);
        ldmatrix_x4(fr.alo[mt], sbase + AL + aoff);
    }
    #pragma unroll
    for (int nt = 0; nt < 4; nt++) {
        uint32_t boff = (uint32_t)((nr + nt * 8) * (LDAB * 2) + (kc * 16 + kb) * 2);
        fr.bhi[nt][0] = lds32(sbase + SM_B_HI + boff);
        fr.bhi[nt][1] = lds32(sbase + SM_B_HI + boff + 16u);
        fr.blo[nt][0] = lds32(sbase + SM_B_LO + boff);
        fr.blo[nt][1] = lds32(sbase + SM_B_LO + boff + 16u);
    }
}

// ---------------------------------------------------------------------------
// Tile load helpers
// ---------------------------------------------------------------------------
__device__ __forceinline__ void ldg_tile(const float4* __restrict__ G4, float4* v,
                                         int atom0, int natoms, int tid) {
    #pragma unroll
    for (int j = 0; j < 8; j++) {
        int i = tid + j * THREADS;
        int a = i >> 5, kq = i & 31;
        int ga = atom0 + a;
        float4 t = make_float4(0.f, 0.f, 0.f, 0.f);
        if (kq < 30 && ga < natoms) t = G4[(size_t)ga * 30 + kq];
        v[j] = t;
    }
}

__device__ __forceinline__ void sts_tile(unsigned char* smem, int bufoff,
                                         const float4* v, int tid) {
    #pragma unroll
    for (int j = 0; j < 8; j++) {
        int i = tid + j * THREADS;
        int a = i >> 5, kq = i & 31;
        float4 t = v[j];

        __nv_bfloat16 hx = __float2bfloat16(t.x);
        __nv_bfloat16 hy = __float2bfloat16(t.y);
        __nv_bfloat16 hz = __float2bfloat16(t.z);
        __nv_bfloat16 hw = __float2bfloat16(t.w);
        __nv_bfloat16 lx = __float2bfloat16(t.x - __bfloat162float(hx));
        __nv_bfloat16 ly = __float2bfloat16(t.y - __bfloat162float(hy));
        __nv_bfloat16 lz = __float2bfloat16(t.z - __bfloat162float(hz));
        __nv_bfloat16 lw = __float2bfloat16(t.w - __bfloat162float(hw));

        unsigned long long hp =
              (unsigned long long)__bfloat16_as_ushort(hx)
            | ((unsigned long long)__bfloat16_as_ushort(hy) << 16)
            | ((unsigned long long)__bfloat16_as_ushort(hz) << 32)
            | ((unsigned long long)__bfloat16_as_ushort(hw) << 48);
        unsigned long long lp =
              (unsigned long long)__bfloat16_as_ushort(lx)
            | ((unsigned long long)__bfloat16_as_ushort(ly) << 16)
            | ((unsigned long long)__bfloat16_as_ushort(lz) << 32)
            | ((unsigned long long)__bfloat16_as_ushort(lw) << 48);

        int off = a * (LDAB * 2) + kq * 8;
        *reinterpret_cast<unsigned long long*>(smem + bufoff + off) = hp;
        *reinterpret_cast<unsigned long long*>(smem + bufoff + A_IMG + off) = lp;
    }
}

// ---------------------------------------------------------------------------
// Main persistent kernel: out[N,120] = G @ M via mma.sync bf16 hi/lo split.
// 1 CTA/SM, 8 warps 2(m)x4(n), warp tile m32 x n32.
// Two-level pipeline: (a) tile-level A-smem double buffer with register LDG
// prefetch; (b) kc-level fragment register double buffer (loads for kc+1
// issue before kc's MMAs -> LDS/ldmatrix latency fully covered).
// ---------------------------------------------------------------------------
__global__ __launch_bounds__(THREADS, 1)
void coupling_mma_kernel(const float* __restrict__ G, float* __restrict__ out,
                         int natoms, int ntiles) {
    extern __shared__ __align__(16) unsigned char smem[];
    uint32_t sbase;
    asm("{ .reg .u64 t; cvta.to.shared.u64 t, %1; cvt.u32.u64 %0, t; }"
        : "=r"(sbase) : "l"(smem));

    int tid = threadIdx.x;
    int lane = tid & 31;
    int wid = tid >> 5;
    int warp_m = wid & 1;
    int warp_n = wid >> 1;
    int m_base = warp_m * 32;
    int n_base = warp_n * 32;

    // Copy B hi/lo images to smem (once per CTA)
    {
        const uint4* bh = reinterpret_cast<const uint4*>(g_Bhi);
        const uint4* bl = reinterpret_cast<const uint4*>(g_Blo);
        uint4* sh = reinterpret_cast<uint4*>(smem + SM_B_HI);
        uint4* sl = reinterpret_cast<uint4*>(smem + SM_B_LO);
        for (int i = tid; i < B_BYTES / 16; i += THREADS) { sh[i] = bh[i]; sl[i] = bl[i]; }
    }

    const float4* G4 = reinterpret_cast<const float4*>(G);

    // per-lane fragment coordinates
    int lrow = m_base + (lane & 15);
    int lkof = (lane >> 4) << 3;
    int nr = n_base + (lane >> 2);
    int kb = (lane & 3) * 2;

    float4 v[8];
    int tile = blockIdx.x;

    // Prologue: fill stage 0
    if (tile < ntiles) {
        ldg_tile(G4, v, tile * TILE_M, natoms, tid);
        sts_tile(smem, 0, v, tid);
    }
    __syncthreads();

    int it = 0;
    for (; tile < ntiles; tile += gridDim.x) {
        int atom0 = tile * TILE_M;
        int ntile = tile + gridDim.x;

        // 1) Prefetch next tile's G into registers
        if (ntile < ntiles) ldg_tile(G4, v, ntile * TILE_M, natoms, tid);

        // 2) MMA mainloop on current stage with kc-level fragment double buffer
        int AH = it * A_BUF;
        int AL = AH + A_IMG;

        float acc[2][4][4];
        #pragma unroll
        for (int mt = 0; mt < 2; mt++)
            #pragma unroll
            for (int nt = 0; nt < 4; nt++)
                #pragma unroll
                for (int q = 0; q < 4; q++) acc[mt][nt][q] = 0.f;

        Frags fr[2];
        load_frags(fr[0], sbase, AH, AL, 0, lrow, lkof, nr, kb);

        #pragma unroll
        for (int kc = 0; kc < 8; kc++) {
            int cur = kc & 1;
            if (kc < 7)
                load_frags(fr[cur ^ 1], sbase, AH, AL, kc + 1, lrow, lkof, nr, kb);
            #pragma unroll
            for (int mt = 0; mt < 2; mt++)
                #pragma unroll
                for (int nt = 0; nt < 4; nt++) {
                    mma_bf16(acc[mt][nt], fr[cur].ahi[mt], fr[cur].bhi[nt]);
                    mma_bf16(acc[mt][nt], fr[cur].ahi[mt], fr[cur].blo[nt]);
                    mma_bf16(acc[mt][nt], fr[cur].alo[mt], fr[cur].bhi[nt]);
                }
        }

        // 3) Convert + store prefetched G into the other stage
        if (ntile < ntiles) sts_tile(smem, (it ^ 1) * A_BUF, v, tid);

        // 4) Store C
        {
            int g = lane >> 2, tg = lane & 3;
            #pragma unroll
            for (int nt = 0; nt < 4; nt++) {
                int w = n_base + nt * 8 + tg * 2;
                if (w < N_FEAT) {
                    #pragma unroll
                    for (int mt = 0; mt < 2; mt++) {
                        int r0 = atom0 + m_base + mt * 16 + g;
                        if (r0 < natoms) {
                            float2 v0 = make_float2(acc[mt][nt][0], acc[mt][nt][1]);
                            *reinterpret_cast<float2*>(out + (size_t)r0 * N_FEAT + w) = v0;
                        }
                        int r1 = r0 + 8;
                        if (r1 < natoms) {
                            float2 v1 = make_float2(acc[mt][nt][2], acc[mt][nt][3]);
                            *reinterpret_cast<float2*>(out + (size_t)r1 * N_FEAT + w) = v1;
                        }
                    }
                }
            }
        }

        __syncthreads();   // stage it consumed by all; stage it^1 fully written
        it ^= 1;
    }
}

// ---------------------------------------------------------------------------
extern "C" void kernel_launch(void* const* d_in, const int* in_sizes, int n_in,
                              void* d_out, int out_size) {
    const float* G    = (const float*)d_in[0];
    const float* f    = (const float*)d_in[1];
    const float* w000 = (const float*)d_in[2];
    const float* w011 = (const float*)d_in[3];
    const float* w101 = (const float*)d_in[4];
    const float* w110 = (const float*)d_in[5];
    const float* w112 = (const float*)d_in[6];
    const float* w202 = (const float*)d_in[7];
    const float* w211 = (const float*)d_in[8];
    const float* wl0  = (const float*)d_in[9];
    const float* wl1  = (const float*)d_in[10];
    const float* wl2  = (const float*)d_in[11];
    float* out = (float*)d_out;

    int natoms = in_sizes[0] / N_FEAT;
    int ntiles = (natoms + TILE_M - 1) / TILE_M;

    build_B_fused<<<(128 * LDAB + 255) / 256, 256>>>(
        f, w000, w011, w101, w110, w112, w202, w211, wl0, wl1, wl2);

    cudaFuncSetAttribute(coupling_mma_kernel,
                         cudaFuncAttributeMaxDynamicSharedMemorySize, SM_TOTAL);
    int grid = ntiles < GRID_CTAS ? ntiles : GRID_CTAS;
    coupling_mma_kernel<<<grid, THREADS, SM_TOTAL>>>(G, out, natoms, ntiles);
}